// round 5
// baseline (speedup 1.0000x reference)
#include <cuda_runtime.h>
#include <cuda_bf16.h>

// ---------------- problem constants ----------------
#define K_CODES 512
#define D_DIM   64
#define NPTS    65536          // 64*32*32
#define HW      1024           // 32*32
#define CHW     65536          // 64*1024
#define BETA_C  0.25f
#define DECAY_C 0.99f
#define OMD_C   0.01f
#define EPS_C   1e-5f
#define TAU     0.04f          // rescue threshold (>> worst-case 3-term bf16 error)

// output layout (float32, tuple order)
#define OFF_Q    1
#define OFF_PERP 4194305
#define OFF_IDX  4194306
#define OFF_CS   4259842
#define OFF_W    4260354
#define OFF_E    4293122

// ---------------- scratch (zero-init at load; kernels restore zero) --------
__device__ float g_counts[K_CODES];
__device__ float g_dw[K_CODES * D_DIM];
__device__ float g_ncs[K_CODES];
__device__ float g_loss_acc;
__device__ float g_nrm[K_CODES];
__device__ int   g_rescue_pts[NPTS];
__device__ int   g_rescue_cnt;
__device__ __nv_bfloat16 g_Ah[NPTS * D_DIM];    // 8MB  x high bf16
__device__ __nv_bfloat16 g_Al[NPTS * D_DIM];    // 8MB  x residual bf16
__device__ __nv_bfloat16 g_Bh[K_CODES * D_DIM];
__device__ __nv_bfloat16 g_Bl[K_CODES * D_DIM];

// ---------------- helpers ----------------
__device__ __forceinline__ void red_add_v4(float* p, float a, float b, float c, float d) {
    asm volatile("red.global.add.v4.f32 [%0], {%1, %2, %3, %4};"
                 :: "l"(p), "f"(a), "f"(b), "f"(c), "f"(d) : "memory");
}
__device__ __forceinline__ unsigned smem_u32(const void* p) {
    unsigned a;
    asm("{ .reg .u64 t; cvta.to.shared.u64 t, %1; cvt.u32.u64 %0, t; }" : "=r"(a) : "l"(p));
    return a;
}
__device__ __forceinline__ unsigned pack_bf(__nv_bfloat16 a, __nv_bfloat16 b) {
    return (unsigned)__bfloat16_as_ushort(a) | ((unsigned)__bfloat16_as_ushort(b) << 16);
}
#define SW128(o) ((o) ^ (((o) >> 3) & 0x70))

// warp-level bf16 MMA (sm_80+ baseline, no 'a' target needed)
__device__ __forceinline__ void mma_bf16(float* c, const unsigned* a,
                                         unsigned b0, unsigned b1) {
    asm volatile(
        "mma.sync.aligned.m16n8k16.row.col.f32.bf16.bf16.f32 "
        "{%0,%1,%2,%3}, {%4,%5,%6,%7}, {%8,%9}, {%0,%1,%2,%3};"
        : "+f"(c[0]), "+f"(c[1]), "+f"(c[2]), "+f"(c[3])
        : "r"(a[0]), "r"(a[1]), "r"(a[2]), "r"(a[3]), "r"(b0), "r"(b1));
}
__device__ __forceinline__ void ldmx2(unsigned& r0, unsigned& r1, unsigned saddr) {
    asm volatile("ldmatrix.sync.aligned.m8n8.x2.shared.b16 {%0,%1}, [%2];"
                 : "=r"(r0), "=r"(r1) : "r"(saddr));
}
// track best/second-best with ascending-index tie preference
__device__ __forceinline__ void upd(float& best, float& sec, int& idx, float d, int c) {
    if (d < best) { sec = best; best = d; idx = c; }
    else if (d < sec) { sec = d; }
}

// ---------------- K1a: convert x -> bf16 hi/lo, [point][dim] ----------------
__global__ __launch_bounds__(512)
void vq_conv_x(const float* __restrict__ in) {
    const int p  = blockIdx.x * 512 + threadIdx.x;
    const int b  = p >> 10, hw = p & 1023;
    const float* x = in + b * CHW + hw;
    uint4* Ah = (uint4*)g_Ah;
    uint4* Al = (uint4*)g_Al;
    #pragma unroll
    for (int j = 0; j < 8; ++j) {
        unsigned h[4], l[4];
        #pragma unroll
        for (int q = 0; q < 4; ++q) {
            float v0 = x[(8 * j + 2 * q) * HW];
            float v1 = x[(8 * j + 2 * q + 1) * HW];
            __nv_bfloat16 h0 = __float2bfloat16(v0), h1 = __float2bfloat16(v1);
            __nv_bfloat16 l0 = __float2bfloat16(v0 - __bfloat162float(h0));
            __nv_bfloat16 l1 = __float2bfloat16(v1 - __bfloat162float(h1));
            h[q] = pack_bf(h0, h1);
            l[q] = pack_bf(l0, l1);
        }
        Ah[p * 8 + j] = make_uint4(h[0], h[1], h[2], h[3]);
        Al[p * 8 + j] = make_uint4(l[0], l[1], l[2], l[3]);
    }
}

// ---------------- K1b: convert embedding -> bf16 hi/lo + fp32 norms --------
__global__ __launch_bounds__(128)
void vq_conv_e(const float* __restrict__ emb) {
    const int k = blockIdx.x * 128 + threadIdx.x;   // grid 4 -> 512
    const float* e = emb + k * D_DIM;
    uint4* Bh = (uint4*)g_Bh;
    uint4* Bl = (uint4*)g_Bl;
    float s = 0.0f;
    #pragma unroll
    for (int j = 0; j < 8; ++j) {
        unsigned h[4], l[4];
        #pragma unroll
        for (int q = 0; q < 4; ++q) {
            float v0 = e[8 * j + 2 * q];
            float v1 = e[8 * j + 2 * q + 1];
            s = fmaf(v0, v0, s);
            s = fmaf(v1, v1, s);
            __nv_bfloat16 h0 = __float2bfloat16(v0), h1 = __float2bfloat16(v1);
            __nv_bfloat16 l0 = __float2bfloat16(v0 - __bfloat162float(h0));
            __nv_bfloat16 l1 = __float2bfloat16(v1 - __bfloat162float(h1));
            h[q] = pack_bf(h0, h1);
            l[q] = pack_bf(l0, l1);
        }
        Bh[k * 8 + j] = make_uint4(h[0], h[1], h[2], h[3]);
        Bl[k * 8 + j] = make_uint4(l[0], l[1], l[2], l[3]);
    }
    g_nrm[k] = s;
}

// ---------------- K2: mma.sync GEMM + argmin -------------------------------
// 128 CTAs x 512 thr (16 warps). Warp handles 16 points/iter, 2 iters.
// smem: nrm 2KB @0 | Bh 64KB @2048 | Bl 64KB @67584  -> 133120 B
#define SM_NRM 0
#define SM_BH  2048
#define SM_BL  67584
#define SMEM_SZ 133120

__global__ __launch_bounds__(512, 1)
void vq_gemm_argmin(float* __restrict__ out_idx) {
    extern __shared__ char smem[];
    const unsigned sb = smem_u32(smem);
    const int tid  = threadIdx.x;
    const int wid  = tid >> 5;
    const int lane = tid & 31;

    // stage codebook (swizzled) + norms once per CTA
    {
        const uint4* bh = (const uint4*)g_Bh;
        const uint4* bl = (const uint4*)g_Bl;
        #pragma unroll
        for (int i = tid; i < K_CODES * 8; i += 512) {
            unsigned off = SW128((unsigned)(i * 16));
            *(uint4*)(smem + SM_BH + off) = bh[i];
            *(uint4*)(smem + SM_BL + off) = bl[i];
        }
        float* nsh = (float*)(smem + SM_NRM);
        if (tid < K_CODES) nsh[tid] = g_nrm[tid];
    }
    __syncthreads();

    const float* nrm_sh = (const float*)(smem + SM_NRM);
    const int r    = lane & 7;            // ldmatrix source row within tile
    const int half = (lane >> 3) & 1;     // 0: k0-7 chunk, 1: k8-15 chunk
    const unsigned lane_rel = (unsigned)(r * 128);
    const unsigned qk  = lane & 3;        // quad position
    const unsigned qr  = lane >> 2;       // row-in-group 0..7

    for (int it = 0; it < 2; ++it) {
        const int p0 = blockIdx.x * 512 + it * 256 + wid * 16;

        // A fragments for 4 k-steps, hi+lo (direct LDG.32, L2-hot)
        unsigned ah[16], al[16];
        {
            const __nv_bfloat16* A0 = g_Ah + (size_t)(p0 + qr) * D_DIM;
            const __nv_bfloat16* A1 = g_Al + (size_t)(p0 + qr) * D_DIM;
            #pragma unroll
            for (int kk = 0; kk < 4; ++kk) {
                const int e0 = kk * 16 + 2 * qk;
                ah[kk*4+0] = *(const unsigned*)(A0 + e0);
                ah[kk*4+1] = *(const unsigned*)(A0 + 8 * D_DIM + e0);
                ah[kk*4+2] = *(const unsigned*)(A0 + e0 + 8);
                ah[kk*4+3] = *(const unsigned*)(A0 + 8 * D_DIM + e0 + 8);
                al[kk*4+0] = *(const unsigned*)(A1 + e0);
                al[kk*4+1] = *(const unsigned*)(A1 + 8 * D_DIM + e0);
                al[kk*4+2] = *(const unsigned*)(A1 + e0 + 8);
                al[kk*4+3] = *(const unsigned*)(A1 + 8 * D_DIM + e0 + 8);
            }
        }

        float best0 = 3.4e38f, sec0 = 3.4e38f;
        float best1 = 3.4e38f, sec1 = 3.4e38f;
        int idx0 = 0, idx1 = 0;

        #pragma unroll 1
        for (int nt = 0; nt < 64; ++nt) {
            float c[4] = {0.f, 0.f, 0.f, 0.f};
            const unsigned ntoff = (unsigned)(nt * 1024) + lane_rel;
            #pragma unroll
            for (int kk = 0; kk < 4; ++kk) {
                const unsigned rel = ntoff + (((unsigned)(kk * 32 + half * 16)) ^ (unsigned)(r * 16));
                unsigned bh0, bh1, bl0, bl1;
                ldmx2(bh0, bh1, sb + SM_BH + rel);
                ldmx2(bl0, bl1, sb + SM_BL + rel);
                mma_bf16(c, &ah[kk*4], bh0, bh1);   // h . eh
                mma_bf16(c, &ah[kk*4], bl0, bl1);   // h . el
                mma_bf16(c, &al[kk*4], bh0, bh1);   // l . eh
            }
            const int colb = nt * 8 + 2 * (int)qk;
            const float n0 = nrm_sh[colb];
            const float n1 = nrm_sh[colb + 1];
            upd(best0, sec0, idx0, fmaf(-2.f, c[0], n0), colb);
            upd(best0, sec0, idx0, fmaf(-2.f, c[1], n1), colb + 1);
            upd(best1, sec1, idx1, fmaf(-2.f, c[2], n0), colb);
            upd(best1, sec1, idx1, fmaf(-2.f, c[3], n1), colb + 1);
        }

        // merge across the 4 lanes of each quad (rows qr and qr+8)
        #pragma unroll
        for (int o = 1; o <= 2; o <<= 1) {
            float ob = __shfl_xor_sync(0xFFFFFFFFu, best0, o);
            float os = __shfl_xor_sync(0xFFFFFFFFu, sec0,  o);
            int   oi = __shfl_xor_sync(0xFFFFFFFFu, idx0,  o);
            if (ob < best0 || (ob == best0 && oi < idx0)) {
                sec0 = fminf(best0, os); best0 = ob; idx0 = oi;
            } else sec0 = fminf(sec0, ob);
            ob = __shfl_xor_sync(0xFFFFFFFFu, best1, o);
            os = __shfl_xor_sync(0xFFFFFFFFu, sec1,  o);
            oi = __shfl_xor_sync(0xFFFFFFFFu, idx1,  o);
            if (ob < best1 || (ob == best1 && oi < idx1)) {
                sec1 = fminf(best1, os); best1 = ob; idx1 = oi;
            } else sec1 = fminf(sec1, ob);
        }

        if (qk == 0) {
            const int pA = p0 + (int)qr;
            const int pB = pA + 8;
            out_idx[pA] = (float)idx0;
            out_idx[pB] = (float)idx1;
            if (sec0 - best0 < TAU) {
                int s = atomicAdd(&g_rescue_cnt, 1);
                g_rescue_pts[s] = pA;
            }
            if (sec1 - best1 < TAU) {
                int s = atomicAdd(&g_rescue_cnt, 1);
                g_rescue_pts[s] = pB;
            }
        }
    }
}

// ---------------- K2b: exact fp32 rescue for near-ties ---------------------
__global__ __launch_bounds__(256)
void vq_rescue(const float* __restrict__ in, const float* __restrict__ emb,
               float* __restrict__ out_idx) {
    const int cnt    = g_rescue_cnt;
    const int lane   = threadIdx.x & 31;
    const int gwarp  = (blockIdx.x * 256 + threadIdx.x) >> 5;
    const int nwarps = gridDim.x * 8;

    for (int itm = gwarp; itm < cnt; itm += nwarps) {
        const int p  = g_rescue_pts[itm];
        const int b  = p >> 10, hw = p & 1023;
        const float* xin = in + b * CHW + hw;
        float x[D_DIM];
        #pragma unroll
        for (int c = 0; c < D_DIM; ++c) x[c] = __ldg(xin + c * HW);

        float bd = 3.4e38f; int bi = 0x7fffffff;
        #pragma unroll 1
        for (int kk = 0; kk < 16; ++kk) {
            const int code = kk * 32 + lane;
            const float4* er = (const float4*)(emb + code * D_DIM);
            float s = 0.0f;
            #pragma unroll
            for (int j = 0; j < 16; ++j) {
                float4 e4 = __ldg(er + j);
                float d0 = x[4 * j + 0] - e4.x;
                float d1 = x[4 * j + 1] - e4.y;
                float d2 = x[4 * j + 2] - e4.z;
                float d3 = x[4 * j + 3] - e4.w;
                s = fmaf(d0, d0, s); s = fmaf(d1, d1, s);
                s = fmaf(d2, d2, s); s = fmaf(d3, d3, s);
            }
            if (s < bd) { bd = s; bi = code; }
        }
        #pragma unroll
        for (int off = 16; off > 0; off >>= 1) {
            float od = __shfl_xor_sync(0xFFFFFFFFu, bd, off);
            int   oi = __shfl_xor_sync(0xFFFFFFFFu, bi, off);
            if (od < bd || (od == bd && oi < bi)) { bd = od; bi = oi; }
        }
        if (lane == 0) out_idx[p] = (float)bi;
    }
}

// ---------------- K3: quantize + exact loss + segment sums ----------------
__global__ __launch_bounds__(512)
void vq_epilogue(const float* __restrict__ in, const float* __restrict__ emb,
                 const float* __restrict__ idxf, float* __restrict__ out_q) {
    const int p  = blockIdx.x * 512 + threadIdx.x;
    const int b  = p >> 10, hw = p & 1023;
    const float* xin = in + b * CHW + hw;
    const int best = (int)idxf[p];

    const float4* erow  = (const float4*)(emb + best * D_DIM);
    float*        qout  = out_q + b * CHW + hw;
    float*        dwrow = g_dw + best * D_DIM;
    float lsum = 0.0f;
    #pragma unroll
    for (int j = 0; j < 16; ++j) {
        float4 e4 = __ldg(erow + j);
        const int c = 4 * j;
        float x0 = xin[(c + 0) * HW];
        float x1 = xin[(c + 1) * HW];
        float x2 = xin[(c + 2) * HW];
        float x3 = xin[(c + 3) * HW];
        float d0 = e4.x - x0, d1 = e4.y - x1, d2 = e4.z - x2, d3 = e4.w - x3;
        qout[(c + 0) * HW] = x0 + d0;
        qout[(c + 1) * HW] = x1 + d1;
        qout[(c + 2) * HW] = x2 + d2;
        qout[(c + 3) * HW] = x3 + d3;
        lsum = fmaf(d0, d0, lsum); lsum = fmaf(d1, d1, lsum);
        lsum = fmaf(d2, d2, lsum); lsum = fmaf(d3, d3, lsum);
        red_add_v4(dwrow + c, x0, x1, x2, x3);
    }
    #pragma unroll
    for (int o = 16; o > 0; o >>= 1) lsum += __shfl_xor_sync(0xFFFFFFFFu, lsum, o);
    if ((threadIdx.x & 31) == 0) atomicAdd(&g_loss_acc, lsum);
    atomicAdd(&g_counts[best], 1.0f);
}

// ---------------- K4a: single-CTA reductions + scalars --------------------
__global__ __launch_bounds__(512, 1)
void vq_finA_kernel(const float* __restrict__ ema_cs, float* __restrict__ out) {
    __shared__ float red[K_CODES];
    const int k = threadIdx.x;

    const float cnt = g_counts[k];
    const float raw = ema_cs[k] * DECAY_C + OMD_C * cnt;

    red[k] = raw;
    __syncthreads();
    #pragma unroll
    for (int o = 256; o > 0; o >>= 1) {
        if (k < o) red[k] += red[k + o];
        __syncthreads();
    }
    const float n = red[0];
    __syncthreads();

    const float ncs = (raw + EPS_C) / (n + (float)K_CODES * EPS_C) * n;
    g_ncs[k] = ncs;
    out[OFF_CS + k] = ncs;

    const float pprob = cnt * (1.0f / (float)NPTS);
    red[k] = pprob * logf(pprob + 1e-10f);
    __syncthreads();
    #pragma unroll
    for (int o = 256; o > 0; o >>= 1) {
        if (k < o) red[k] += red[k + o];
        __syncthreads();
    }
    if (k == 0) {
        out[OFF_PERP] = expf(-red[0]);
        out[0] = BETA_C * g_loss_acc / (float)(NPTS * D_DIM);
        g_loss_acc   = 0.0f;
        g_rescue_cnt = 0;
    }
    g_counts[k] = 0.0f;
}

// ---------------- K4b: parallel EMA-w / new-embedding ---------------------
__global__ __launch_bounds__(512)
void vq_finB_kernel(const float* __restrict__ ema_w, float* __restrict__ out) {
    const int i = blockIdx.x * 512 + threadIdx.x;   // < 32768
    const float w = ema_w[i] * DECAY_C + OMD_C * g_dw[i];
    g_dw[i] = 0.0f;
    out[OFF_W + i] = w;
    out[OFF_E + i] = w / g_ncs[i >> 6];
}

// ---------------- launch ----------------
extern "C" void kernel_launch(void* const* d_in, const int* in_sizes, int n_in,
                              void* d_out, int out_size) {
    const float* in     = (const float*)d_in[0];
    const float* emb    = (const float*)d_in[1];
    const float* ema_w  = (const float*)d_in[2];
    const float* ema_cs = (const float*)d_in[3];
    float* out = (float*)d_out;

    cudaFuncSetAttribute(vq_gemm_argmin,
                         cudaFuncAttributeMaxDynamicSharedMemorySize, SMEM_SZ);

    vq_conv_x<<<128, 512>>>(in);
    vq_conv_e<<<4, 128>>>(emb);
    vq_gemm_argmin<<<128, 512, SMEM_SZ>>>(out + OFF_IDX);
    vq_rescue<<<32, 256>>>(in, emb, out + OFF_IDX);
    vq_epilogue<<<128, 512>>>(in, emb, out + OFF_IDX, out + OFF_Q);
    vq_finA_kernel<<<1, 512>>>(ema_cs, out);
    vq_finB_kernel<<<64, 512>>>(ema_w, out);
}

// round 6
// speedup vs baseline: 1.5104x; 1.5104x over previous
#include <cuda_runtime.h>
#include <cuda_bf16.h>

// ---------------- problem constants ----------------
#define K_CODES 512
#define D_DIM   64
#define NPTS    65536          // 64*32*32
#define HW      1024           // 32*32
#define CHW     65536          // 64*1024
#define BETA_C  0.25f
#define DECAY_C 0.99f
#define OMD_C   0.01f
#define EPS_C   1e-5f
#define TAU     0.02f          // rescue threshold (>> 20x realistic 3-term bf16 error)

// output layout (float32, tuple order)
#define OFF_Q    1
#define OFF_PERP 4194305
#define OFF_IDX  4194306
#define OFF_CS   4259842
#define OFF_W    4260354
#define OFF_E    4293122

// ---------------- scratch (zero-init at load; kernels restore zero) --------
__device__ float g_counts[K_CODES];
__device__ float g_dw[K_CODES * D_DIM];
__device__ float g_ncs[K_CODES];
__device__ float g_loss_acc;
__device__ float g_nrm[K_CODES];
__device__ int   g_rescue_pts[NPTS];
__device__ int   g_rescue_cnt;
__device__ __nv_bfloat16 g_Ah[NPTS * D_DIM];    // 8MB  x high bf16
__device__ __nv_bfloat16 g_Al[NPTS * D_DIM];    // 8MB  x residual bf16
__device__ __nv_bfloat16 g_Bh[K_CODES * D_DIM];
__device__ __nv_bfloat16 g_Bl[K_CODES * D_DIM];

// ---------------- helpers ----------------
__device__ __forceinline__ void red_add_v4(float* p, float a, float b, float c, float d) {
    asm volatile("red.global.add.v4.f32 [%0], {%1, %2, %3, %4};"
                 :: "l"(p), "f"(a), "f"(b), "f"(c), "f"(d) : "memory");
}
__device__ __forceinline__ unsigned smem_u32(const void* p) {
    unsigned a;
    asm("{ .reg .u64 t; cvta.to.shared.u64 t, %1; cvt.u32.u64 %0, t; }" : "=r"(a) : "l"(p));
    return a;
}
__device__ __forceinline__ unsigned pack_bf(__nv_bfloat16 a, __nv_bfloat16 b) {
    return (unsigned)__bfloat16_as_ushort(a) | ((unsigned)__bfloat16_as_ushort(b) << 16);
}
#define SW128(o) ((o) ^ (((o) >> 3) & 0x70))

// warp-level bf16 MMA (sm_80+ baseline PTX, no 'a' suffix needed)
__device__ __forceinline__ void mma_bf16(float* c, const unsigned* a,
                                         unsigned b0, unsigned b1) {
    asm volatile(
        "mma.sync.aligned.m16n8k16.row.col.f32.bf16.bf16.f32 "
        "{%0,%1,%2,%3}, {%4,%5,%6,%7}, {%8,%9}, {%0,%1,%2,%3};"
        : "+f"(c[0]), "+f"(c[1]), "+f"(c[2]), "+f"(c[3])
        : "r"(a[0]), "r"(a[1]), "r"(a[2]), "r"(a[3]), "r"(b0), "r"(b1));
}
__device__ __forceinline__ void ldmx2(unsigned& r0, unsigned& r1, unsigned saddr) {
    asm volatile("ldmatrix.sync.aligned.m8n8.x2.shared.b16 {%0,%1}, [%2];"
                 : "=r"(r0), "=r"(r1) : "r"(saddr));
}
__device__ __forceinline__ void upd(float& best, float& sec, int& idx, float d, int c) {
    if (d < best) { sec = best; best = d; idx = c; }
    else if (d < sec) { sec = d; }
}

// ---------------- K1a: convert x -> bf16 hi/lo, [point][dim] ----------------
__global__ __launch_bounds__(512)
void vq_conv_x(const float* __restrict__ in) {
    const int p  = blockIdx.x * 512 + threadIdx.x;
    const int b  = p >> 10, hw = p & 1023;
    const float* x = in + b * CHW + hw;
    uint4* Ah = (uint4*)g_Ah;
    uint4* Al = (uint4*)g_Al;
    #pragma unroll
    for (int j = 0; j < 8; ++j) {
        unsigned h[4], l[4];
        #pragma unroll
        for (int q = 0; q < 4; ++q) {
            float v0 = x[(8 * j + 2 * q) * HW];
            float v1 = x[(8 * j + 2 * q + 1) * HW];
            __nv_bfloat16 h0 = __float2bfloat16(v0), h1 = __float2bfloat16(v1);
            __nv_bfloat16 l0 = __float2bfloat16(v0 - __bfloat162float(h0));
            __nv_bfloat16 l1 = __float2bfloat16(v1 - __bfloat162float(h1));
            h[q] = pack_bf(h0, h1);
            l[q] = pack_bf(l0, l1);
        }
        Ah[p * 8 + j] = make_uint4(h[0], h[1], h[2], h[3]);
        Al[p * 8 + j] = make_uint4(l[0], l[1], l[2], l[3]);
    }
}

// ---------------- K1b: convert embedding -> bf16 hi/lo + fp32 norms --------
__global__ __launch_bounds__(128)
void vq_conv_e(const float* __restrict__ emb) {
    const int k = blockIdx.x * 128 + threadIdx.x;   // grid 4 -> 512
    const float* e = emb + k * D_DIM;
    uint4* Bh = (uint4*)g_Bh;
    uint4* Bl = (uint4*)g_Bl;
    float s = 0.0f;
    #pragma unroll
    for (int j = 0; j < 8; ++j) {
        unsigned h[4], l[4];
        #pragma unroll
        for (int q = 0; q < 4; ++q) {
            float v0 = e[8 * j + 2 * q];
            float v1 = e[8 * j + 2 * q + 1];
            s = fmaf(v0, v0, s);
            s = fmaf(v1, v1, s);
            __nv_bfloat16 h0 = __float2bfloat16(v0), h1 = __float2bfloat16(v1);
            __nv_bfloat16 l0 = __float2bfloat16(v0 - __bfloat162float(h0));
            __nv_bfloat16 l1 = __float2bfloat16(v1 - __bfloat162float(h1));
            h[q] = pack_bf(h0, h1);
            l[q] = pack_bf(l0, l1);
        }
        Bh[k * 8 + j] = make_uint4(h[0], h[1], h[2], h[3]);
        Bl[k * 8 + j] = make_uint4(l[0], l[1], l[2], l[3]);
    }
    g_nrm[k] = s;
}

// ---------------- K2: mma.sync GEMM + argmin -------------------------------
// 128 CTAs x 512 thr (16 warps). Each warp: 32 points (two m16 tiles), 512 codes.
// smem: nrm 2KB @0 | Bh 64KB @2048 | Bl 64KB @67584  -> 133120 B
#define SM_NRM 0
#define SM_BH  2048
#define SM_BL  67584
#define SMEM_SZ 133120

__global__ __launch_bounds__(512, 1)
void vq_gemm_argmin(float* __restrict__ out_idx) {
    extern __shared__ char smem[];
    const unsigned sb = smem_u32(smem);
    const int tid  = threadIdx.x;
    const int wid  = tid >> 5;
    const int lane = tid & 31;

    // stage codebook (swizzled) + norms once per CTA
    {
        const uint4* bh = (const uint4*)g_Bh;
        const uint4* bl = (const uint4*)g_Bl;
        #pragma unroll
        for (int i = tid; i < K_CODES * 8; i += 512) {
            unsigned off = SW128((unsigned)(i * 16));
            *(uint4*)(smem + SM_BH + off) = bh[i];
            *(uint4*)(smem + SM_BL + off) = bl[i];
        }
        float* nsh = (float*)(smem + SM_NRM);
        if (tid < K_CODES) nsh[tid] = g_nrm[tid];
    }
    __syncthreads();

    const float* nrm_sh = (const float*)(smem + SM_NRM);
    const int r    = lane & 7;
    const int half = (lane >> 3) & 1;
    const unsigned lane_rel = (unsigned)(r * 128);
    const unsigned qk = lane & 3;
    const unsigned qr = lane >> 2;

    const int p0 = blockIdx.x * 512 + wid * 32;   // 32 points per warp

    // A fragments for both 16-row tiles, 4 k-steps, hi+lo
    unsigned ah[2][16], al[2][16];
    #pragma unroll
    for (int t = 0; t < 2; ++t) {
        const __nv_bfloat16* A0 = g_Ah + (size_t)(p0 + t * 16 + qr) * D_DIM;
        const __nv_bfloat16* A1 = g_Al + (size_t)(p0 + t * 16 + qr) * D_DIM;
        #pragma unroll
        for (int kk = 0; kk < 4; ++kk) {
            const int e0 = kk * 16 + 2 * (int)qk;
            ah[t][kk*4+0] = *(const unsigned*)(A0 + e0);
            ah[t][kk*4+1] = *(const unsigned*)(A0 + 8 * D_DIM + e0);
            ah[t][kk*4+2] = *(const unsigned*)(A0 + e0 + 8);
            ah[t][kk*4+3] = *(const unsigned*)(A0 + 8 * D_DIM + e0 + 8);
            al[t][kk*4+0] = *(const unsigned*)(A1 + e0);
            al[t][kk*4+1] = *(const unsigned*)(A1 + 8 * D_DIM + e0);
            al[t][kk*4+2] = *(const unsigned*)(A1 + e0 + 8);
            al[t][kk*4+3] = *(const unsigned*)(A1 + 8 * D_DIM + e0 + 8);
        }
    }

    // slot s = t*2 + rowgroup (rowgroup 0: row qr, 1: row qr+8)
    float best[4] = {3.4e38f, 3.4e38f, 3.4e38f, 3.4e38f};
    float sec [4] = {3.4e38f, 3.4e38f, 3.4e38f, 3.4e38f};
    int   idx [4] = {0, 0, 0, 0};

    #pragma unroll 1
    for (int nt = 0; nt < 64; ++nt) {
        float c0[4] = {0.f, 0.f, 0.f, 0.f};
        float c1[4] = {0.f, 0.f, 0.f, 0.f};
        const unsigned ntoff = (unsigned)(nt * 1024) + lane_rel;
        #pragma unroll
        for (int kk = 0; kk < 4; ++kk) {
            const unsigned rel = ntoff + (((unsigned)(kk * 32 + half * 16)) ^ (unsigned)(r * 16));
            unsigned bh0, bh1, bl0, bl1;
            ldmx2(bh0, bh1, sb + SM_BH + rel);
            ldmx2(bl0, bl1, sb + SM_BL + rel);
            mma_bf16(c0, &ah[0][kk*4], bh0, bh1);
            mma_bf16(c0, &ah[0][kk*4], bl0, bl1);
            mma_bf16(c0, &al[0][kk*4], bh0, bh1);
            mma_bf16(c1, &ah[1][kk*4], bh0, bh1);
            mma_bf16(c1, &ah[1][kk*4], bl0, bl1);
            mma_bf16(c1, &al[1][kk*4], bh0, bh1);
        }
        const int colb = nt * 8 + 2 * (int)qk;
        const float n0 = nrm_sh[colb];
        const float n1 = nrm_sh[colb + 1];
        upd(best[0], sec[0], idx[0], fmaf(-2.f, c0[0], n0), colb);
        upd(best[0], sec[0], idx[0], fmaf(-2.f, c0[1], n1), colb + 1);
        upd(best[1], sec[1], idx[1], fmaf(-2.f, c0[2], n0), colb);
        upd(best[1], sec[1], idx[1], fmaf(-2.f, c0[3], n1), colb + 1);
        upd(best[2], sec[2], idx[2], fmaf(-2.f, c1[0], n0), colb);
        upd(best[2], sec[2], idx[2], fmaf(-2.f, c1[1], n1), colb + 1);
        upd(best[3], sec[3], idx[3], fmaf(-2.f, c1[2], n0), colb);
        upd(best[3], sec[3], idx[3], fmaf(-2.f, c1[3], n1), colb + 1);
    }

    // merge across the 4 lanes of each quad
    #pragma unroll
    for (int s = 0; s < 4; ++s) {
        #pragma unroll
        for (int o = 1; o <= 2; o <<= 1) {
            float ob = __shfl_xor_sync(0xFFFFFFFFu, best[s], o);
            float os = __shfl_xor_sync(0xFFFFFFFFu, sec[s],  o);
            int   oi = __shfl_xor_sync(0xFFFFFFFFu, idx[s],  o);
            if (ob < best[s] || (ob == best[s] && oi < idx[s])) {
                sec[s] = fminf(best[s], os); best[s] = ob; idx[s] = oi;
            } else sec[s] = fminf(sec[s], ob);
        }
    }

    if (qk == 0) {
        #pragma unroll
        for (int s = 0; s < 4; ++s) {
            const int p = p0 + (s >> 1) * 16 + (int)qr + (s & 1) * 8;
            out_idx[p] = (float)idx[s];
            if (sec[s] - best[s] < TAU) {
                int slot = atomicAdd(&g_rescue_cnt, 1);
                g_rescue_pts[slot] = p;
            }
        }
    }
}

// ---------------- K2b: exact fp32 rescue for near-ties ---------------------
// 128 CTAs x 256 thr = 1024 warps; one point per warp (expected ~200 rescues)
__global__ __launch_bounds__(256)
void vq_rescue(const float* __restrict__ in, const float* __restrict__ emb,
               float* __restrict__ out_idx) {
    const int cnt    = g_rescue_cnt;
    const int lane   = threadIdx.x & 31;
    const int gwarp  = (blockIdx.x * 256 + threadIdx.x) >> 5;
    const int nwarps = gridDim.x * 8;

    for (int itm = gwarp; itm < cnt; itm += nwarps) {
        const int p  = g_rescue_pts[itm];
        const int b  = p >> 10, hw = p & 1023;
        const float* xin = in + b * CHW + hw;
        float x[D_DIM];
        #pragma unroll
        for (int c = 0; c < D_DIM; ++c) x[c] = __ldg(xin + c * HW);

        float bd = 3.4e38f; int bi = 0x7fffffff;
        #pragma unroll 1
        for (int kk = 0; kk < 16; ++kk) {
            const int code = kk * 32 + lane;
            const float4* er = (const float4*)(emb + code * D_DIM);
            float s0 = 0.0f, s1 = 0.0f;
            #pragma unroll
            for (int j = 0; j < 16; ++j) {
                float4 e4 = __ldg(er + j);
                s0 = fmaf(x[4 * j + 0], e4.x, s0);
                s1 = fmaf(x[4 * j + 1], e4.y, s1);
                s0 = fmaf(x[4 * j + 2], e4.z, s0);
                s1 = fmaf(x[4 * j + 3], e4.w, s1);
            }
            const float d = fmaf(-2.0f, s0 + s1, __ldg(&g_nrm[code]));
            if (d < bd) { bd = d; bi = code; }
        }
        #pragma unroll
        for (int off = 16; off > 0; off >>= 1) {
            float od = __shfl_xor_sync(0xFFFFFFFFu, bd, off);
            int   oi = __shfl_xor_sync(0xFFFFFFFFu, bi, off);
            if (od < bd || (od == bd && oi < bi)) { bd = od; bi = oi; }
        }
        if (lane == 0) out_idx[p] = (float)bi;
    }
}

// ---------------- K3: quantize + exact loss + segment sums ----------------
__global__ __launch_bounds__(512)
void vq_epilogue(const float* __restrict__ in, const float* __restrict__ emb,
                 const float* __restrict__ idxf, float* __restrict__ out_q) {
    const int p  = blockIdx.x * 512 + threadIdx.x;
    const int b  = p >> 10, hw = p & 1023;
    const float* xin = in + b * CHW + hw;
    const int best = (int)idxf[p];

    const float4* erow  = (const float4*)(emb + best * D_DIM);
    float*        qout  = out_q + b * CHW + hw;
    float*        dwrow = g_dw + best * D_DIM;
    float lsum = 0.0f;
    #pragma unroll
    for (int j = 0; j < 16; ++j) {
        float4 e4 = __ldg(erow + j);
        const int c = 4 * j;
        float x0 = xin[(c + 0) * HW];
        float x1 = xin[(c + 1) * HW];
        float x2 = xin[(c + 2) * HW];
        float x3 = xin[(c + 3) * HW];
        float d0 = e4.x - x0, d1 = e4.y - x1, d2 = e4.z - x2, d3 = e4.w - x3;
        qout[(c + 0) * HW] = x0 + d0;
        qout[(c + 1) * HW] = x1 + d1;
        qout[(c + 2) * HW] = x2 + d2;
        qout[(c + 3) * HW] = x3 + d3;
        lsum = fmaf(d0, d0, lsum); lsum = fmaf(d1, d1, lsum);
        lsum = fmaf(d2, d2, lsum); lsum = fmaf(d3, d3, lsum);
        red_add_v4(dwrow + c, x0, x1, x2, x3);
    }
    #pragma unroll
    for (int o = 16; o > 0; o >>= 1) lsum += __shfl_xor_sync(0xFFFFFFFFu, lsum, o);
    if ((threadIdx.x & 31) == 0) atomicAdd(&g_loss_acc, lsum);
    atomicAdd(&g_counts[best], 1.0f);
}

// ---------------- K4a: single-CTA reductions + scalars --------------------
__global__ __launch_bounds__(512, 1)
void vq_finA_kernel(const float* __restrict__ ema_cs, float* __restrict__ out) {
    __shared__ float red[K_CODES];
    const int k = threadIdx.x;

    const float cnt = g_counts[k];
    const float raw = ema_cs[k] * DECAY_C + OMD_C * cnt;

    red[k] = raw;
    __syncthreads();
    #pragma unroll
    for (int o = 256; o > 0; o >>= 1) {
        if (k < o) red[k] += red[k + o];
        __syncthreads();
    }
    const float n = red[0];
    __syncthreads();

    const float ncs = (raw + EPS_C) / (n + (float)K_CODES * EPS_C) * n;
    g_ncs[k] = ncs;
    out[OFF_CS + k] = ncs;

    const float pprob = cnt * (1.0f / (float)NPTS);
    red[k] = pprob * logf(pprob + 1e-10f);
    __syncthreads();
    #pragma unroll
    for (int o = 256; o > 0; o >>= 1) {
        if (k < o) red[k] += red[k + o];
        __syncthreads();
    }
    if (k == 0) {
        out[OFF_PERP] = expf(-red[0]);
        out[0] = BETA_C * g_loss_acc / (float)(NPTS * D_DIM);
        g_loss_acc   = 0.0f;
        g_rescue_cnt = 0;
    }
    g_counts[k] = 0.0f;
}

// ---------------- K4b: parallel EMA-w / new-embedding ---------------------
__global__ __launch_bounds__(512)
void vq_finB_kernel(const float* __restrict__ ema_w, float* __restrict__ out) {
    const int i = blockIdx.x * 512 + threadIdx.x;   // < 32768
    const float w = ema_w[i] * DECAY_C + OMD_C * g_dw[i];
    g_dw[i] = 0.0f;
    out[OFF_W + i] = w;
    out[OFF_E + i] = w / g_ncs[i >> 6];
}

// ---------------- launch ----------------
extern "C" void kernel_launch(void* const* d_in, const int* in_sizes, int n_in,
                              void* d_out, int out_size) {
    const float* in     = (const float*)d_in[0];
    const float* emb    = (const float*)d_in[1];
    const float* ema_w  = (const float*)d_in[2];
    const float* ema_cs = (const float*)d_in[3];
    float* out = (float*)d_out;

    cudaFuncSetAttribute(vq_gemm_argmin,
                         cudaFuncAttributeMaxDynamicSharedMemorySize, SMEM_SZ);

    vq_conv_x<<<128, 512>>>(in);
    vq_conv_e<<<4, 128>>>(emb);
    vq_gemm_argmin<<<128, 512, SMEM_SZ>>>(out + OFF_IDX);
    vq_rescue<<<128, 256>>>(in, emb, out + OFF_IDX);
    vq_epilogue<<<128, 512>>>(in, emb, out + OFF_IDX, out + OFF_Q);
    vq_finA_kernel<<<1, 512>>>(ema_cs, out);
    vq_finB_kernel<<<64, 512>>>(ema_w, out);
}

// round 7
// speedup vs baseline: 1.5378x; 1.0182x over previous
#include <cuda_runtime.h>
#include <cuda_bf16.h>

// ---------------- problem constants ----------------
#define K_CODES 512
#define D_DIM   64
#define NPTS    65536          // 64*32*32
#define HW      1024           // 32*32
#define CHW     65536          // 64*1024
#define BETA_C  0.25f
#define DECAY_C 0.99f
#define OMD_C   0.01f
#define EPS_C   1e-5f
#define TAU     0.005f         // rescue threshold (~10x worst-case 3-term bf16 error)

// output layout (float32, tuple order)
#define OFF_Q    1
#define OFF_PERP 4194305
#define OFF_IDX  4194306
#define OFF_CS   4259842
#define OFF_W    4260354
#define OFF_E    4293122

// ---------------- scratch (zero-init at load; kernels restore zero) --------
__device__ float g_counts[K_CODES];
__device__ float g_dw[K_CODES * D_DIM];
__device__ float g_ncs[K_CODES];
__device__ float g_loss_acc;
__device__ float g_nrm[K_CODES];
__device__ int   g_rescue_pts[NPTS];
__device__ int   g_rescue_cnt;
__device__ __nv_bfloat16 g_Ah[NPTS * D_DIM];    // 8MB  x high bf16
__device__ __nv_bfloat16 g_Al[NPTS * D_DIM];    // 8MB  x residual bf16
__device__ __nv_bfloat16 g_Bh[K_CODES * D_DIM];
__device__ __nv_bfloat16 g_Bl[K_CODES * D_DIM];

// ---------------- helpers ----------------
__device__ __forceinline__ void red_add_v4(float* p, float a, float b, float c, float d) {
    asm volatile("red.global.add.v4.f32 [%0], {%1, %2, %3, %4};"
                 :: "l"(p), "f"(a), "f"(b), "f"(c), "f"(d) : "memory");
}
__device__ __forceinline__ unsigned smem_u32(const void* p) {
    unsigned a;
    asm("{ .reg .u64 t; cvta.to.shared.u64 t, %1; cvt.u32.u64 %0, t; }" : "=r"(a) : "l"(p));
    return a;
}
__device__ __forceinline__ unsigned pack_bf(__nv_bfloat16 a, __nv_bfloat16 b) {
    return (unsigned)__bfloat16_as_ushort(a) | ((unsigned)__bfloat16_as_ushort(b) << 16);
}
#define SW128(o) ((o) ^ (((o) >> 3) & 0x70))

// warp-level bf16 MMA (sm_80+ baseline PTX, no 'a' suffix needed)
__device__ __forceinline__ void mma_bf16(float* c, const unsigned* a,
                                         unsigned b0, unsigned b1) {
    asm volatile(
        "mma.sync.aligned.m16n8k16.row.col.f32.bf16.bf16.f32 "
        "{%0,%1,%2,%3}, {%4,%5,%6,%7}, {%8,%9}, {%0,%1,%2,%3};"
        : "+f"(c[0]), "+f"(c[1]), "+f"(c[2]), "+f"(c[3])
        : "r"(a[0]), "r"(a[1]), "r"(a[2]), "r"(a[3]), "r"(b0), "r"(b1));
}
__device__ __forceinline__ void ldmx2(unsigned& r0, unsigned& r1, unsigned saddr) {
    asm volatile("ldmatrix.sync.aligned.m8n8.x2.shared.b16 {%0,%1}, [%2];"
                 : "=r"(r0), "=r"(r1) : "r"(saddr));
}
__device__ __forceinline__ void upd(float& best, float& sec, int& idx, float d, int c) {
    if (d < best) { sec = best; best = d; idx = c; }
    else if (d < sec) { sec = d; }
}

// ---------------- K1a: convert x -> bf16 hi/lo, [point][dim] ----------------
__global__ __launch_bounds__(256)
void vq_conv_x(const float* __restrict__ in) {
    const int p  = blockIdx.x * 256 + threadIdx.x;
    const int b  = p >> 10, hw = p & 1023;
    const float* x = in + b * CHW + hw;
    uint4* Ah = (uint4*)g_Ah;
    uint4* Al = (uint4*)g_Al;
    #pragma unroll
    for (int j = 0; j < 8; ++j) {
        unsigned h[4], l[4];
        #pragma unroll
        for (int q = 0; q < 4; ++q) {
            float v0 = x[(8 * j + 2 * q) * HW];
            float v1 = x[(8 * j + 2 * q + 1) * HW];
            __nv_bfloat16 h0 = __float2bfloat16(v0), h1 = __float2bfloat16(v1);
            __nv_bfloat16 l0 = __float2bfloat16(v0 - __bfloat162float(h0));
            __nv_bfloat16 l1 = __float2bfloat16(v1 - __bfloat162float(h1));
            h[q] = pack_bf(h0, h1);
            l[q] = pack_bf(l0, l1);
        }
        Ah[p * 8 + j] = make_uint4(h[0], h[1], h[2], h[3]);
        Al[p * 8 + j] = make_uint4(l[0], l[1], l[2], l[3]);
    }
}

// ---------------- K1b: convert embedding -> bf16 hi/lo + fp32 norms --------
__global__ __launch_bounds__(128)
void vq_conv_e(const float* __restrict__ emb) {
    const int k = blockIdx.x * 128 + threadIdx.x;   // grid 4 -> 512
    const float* e = emb + k * D_DIM;
    uint4* Bh = (uint4*)g_Bh;
    uint4* Bl = (uint4*)g_Bl;
    float s = 0.0f;
    #pragma unroll
    for (int j = 0; j < 8; ++j) {
        unsigned h[4], l[4];
        #pragma unroll
        for (int q = 0; q < 4; ++q) {
            float v0 = e[8 * j + 2 * q];
            float v1 = e[8 * j + 2 * q + 1];
            s = fmaf(v0, v0, s);
            s = fmaf(v1, v1, s);
            __nv_bfloat16 h0 = __float2bfloat16(v0), h1 = __float2bfloat16(v1);
            __nv_bfloat16 l0 = __float2bfloat16(v0 - __bfloat162float(h0));
            __nv_bfloat16 l1 = __float2bfloat16(v1 - __bfloat162float(h1));
            h[q] = pack_bf(h0, h1);
            l[q] = pack_bf(l0, l1);
        }
        Bh[k * 8 + j] = make_uint4(h[0], h[1], h[2], h[3]);
        Bl[k * 8 + j] = make_uint4(l[0], l[1], l[2], l[3]);
    }
    g_nrm[k] = s;
}

// ---------------- K2: mma.sync GEMM + argmin -------------------------------
// 128 CTAs x 512 thr (16 warps). Each warp: 32 points (two m16 tiles), 512 codes.
// smem: nrm 2KB @0 | Bh 64KB @2048 | Bl 64KB @67584  -> 133120 B
#define SM_NRM 0
#define SM_BH  2048
#define SM_BL  67584
#define SMEM_SZ 133120

__global__ __launch_bounds__(512, 1)
void vq_gemm_argmin(float* __restrict__ out_idx) {
    extern __shared__ char smem[];
    const unsigned sb = smem_u32(smem);
    const int tid  = threadIdx.x;
    const int wid  = tid >> 5;
    const int lane = tid & 31;

    // stage codebook (swizzled) + norms once per CTA
    {
        const uint4* bh = (const uint4*)g_Bh;
        const uint4* bl = (const uint4*)g_Bl;
        #pragma unroll
        for (int i = tid; i < K_CODES * 8; i += 512) {
            unsigned off = SW128((unsigned)(i * 16));
            *(uint4*)(smem + SM_BH + off) = bh[i];
            *(uint4*)(smem + SM_BL + off) = bl[i];
        }
        float* nsh = (float*)(smem + SM_NRM);
        if (tid < K_CODES) nsh[tid] = g_nrm[tid];
    }
    __syncthreads();

    const float* nrm_sh = (const float*)(smem + SM_NRM);
    const int r    = lane & 7;
    const int half = (lane >> 3) & 1;
    const unsigned lane_rel = (unsigned)(r * 128);
    const unsigned qk = lane & 3;
    const unsigned qr = lane >> 2;

    const int p0 = blockIdx.x * 512 + wid * 32;   // 32 points per warp

    // A fragments for both 16-row tiles, 4 k-steps, hi+lo
    unsigned ah[2][16], al[2][16];
    #pragma unroll
    for (int t = 0; t < 2; ++t) {
        const __nv_bfloat16* A0 = g_Ah + (size_t)(p0 + t * 16 + qr) * D_DIM;
        const __nv_bfloat16* A1 = g_Al + (size_t)(p0 + t * 16 + qr) * D_DIM;
        #pragma unroll
        for (int kk = 0; kk < 4; ++kk) {
            const int e0 = kk * 16 + 2 * (int)qk;
            ah[t][kk*4+0] = *(const unsigned*)(A0 + e0);
            ah[t][kk*4+1] = *(const unsigned*)(A0 + 8 * D_DIM + e0);
            ah[t][kk*4+2] = *(const unsigned*)(A0 + e0 + 8);
            ah[t][kk*4+3] = *(const unsigned*)(A0 + 8 * D_DIM + e0 + 8);
            al[t][kk*4+0] = *(const unsigned*)(A1 + e0);
            al[t][kk*4+1] = *(const unsigned*)(A1 + 8 * D_DIM + e0);
            al[t][kk*4+2] = *(const unsigned*)(A1 + e0 + 8);
            al[t][kk*4+3] = *(const unsigned*)(A1 + 8 * D_DIM + e0 + 8);
        }
    }

    // slot s = t*2 + rowgroup (rowgroup 0: row qr, 1: row qr+8)
    float best[4] = {3.4e38f, 3.4e38f, 3.4e38f, 3.4e38f};
    float sec [4] = {3.4e38f, 3.4e38f, 3.4e38f, 3.4e38f};
    int   idx [4] = {0, 0, 0, 0};

    #pragma unroll 1
    for (int nt = 0; nt < 64; ++nt) {
        float c0[4] = {0.f, 0.f, 0.f, 0.f};
        float c1[4] = {0.f, 0.f, 0.f, 0.f};
        const unsigned ntoff = (unsigned)(nt * 1024) + lane_rel;
        #pragma unroll
        for (int kk = 0; kk < 4; ++kk) {
            const unsigned rel = ntoff + (((unsigned)(kk * 32 + half * 16)) ^ (unsigned)(r * 16));
            unsigned bh0, bh1, bl0, bl1;
            ldmx2(bh0, bh1, sb + SM_BH + rel);
            ldmx2(bl0, bl1, sb + SM_BL + rel);
            mma_bf16(c0, &ah[0][kk*4], bh0, bh1);
            mma_bf16(c0, &ah[0][kk*4], bl0, bl1);
            mma_bf16(c0, &al[0][kk*4], bh0, bh1);
            mma_bf16(c1, &ah[1][kk*4], bh0, bh1);
            mma_bf16(c1, &ah[1][kk*4], bl0, bl1);
            mma_bf16(c1, &al[1][kk*4], bh0, bh1);
        }
        const int colb = nt * 8 + 2 * (int)qk;
        const float n0 = nrm_sh[colb];
        const float n1 = nrm_sh[colb + 1];
        upd(best[0], sec[0], idx[0], fmaf(-2.f, c0[0], n0), colb);
        upd(best[0], sec[0], idx[0], fmaf(-2.f, c0[1], n1), colb + 1);
        upd(best[1], sec[1], idx[1], fmaf(-2.f, c0[2], n0), colb);
        upd(best[1], sec[1], idx[1], fmaf(-2.f, c0[3], n1), colb + 1);
        upd(best[2], sec[2], idx[2], fmaf(-2.f, c1[0], n0), colb);
        upd(best[2], sec[2], idx[2], fmaf(-2.f, c1[1], n1), colb + 1);
        upd(best[3], sec[3], idx[3], fmaf(-2.f, c1[2], n0), colb);
        upd(best[3], sec[3], idx[3], fmaf(-2.f, c1[3], n1), colb + 1);
    }

    // merge across the 4 lanes of each quad
    #pragma unroll
    for (int s = 0; s < 4; ++s) {
        #pragma unroll
        for (int o = 1; o <= 2; o <<= 1) {
            float ob = __shfl_xor_sync(0xFFFFFFFFu, best[s], o);
            float os = __shfl_xor_sync(0xFFFFFFFFu, sec[s],  o);
            int   oi = __shfl_xor_sync(0xFFFFFFFFu, idx[s],  o);
            if (ob < best[s] || (ob == best[s] && oi < idx[s])) {
                sec[s] = fminf(best[s], os); best[s] = ob; idx[s] = oi;
            } else sec[s] = fminf(sec[s], ob);
        }
    }

    if (qk == 0) {
        #pragma unroll
        for (int s = 0; s < 4; ++s) {
            const int p = p0 + (s >> 1) * 16 + (int)qr + (s & 1) * 8;
            out_idx[p] = (float)idx[s];
            if (sec[s] - best[s] < TAU) {
                int slot = atomicAdd(&g_rescue_cnt, 1);
                g_rescue_pts[slot] = p;
            }
        }
    }
}

// ---------------- K2b: exact fp32 rescue for near-ties ---------------------
// 128 CTAs x 256 thr = 1024 warps; about one point per warp
__global__ __launch_bounds__(256)
void vq_rescue(const float* __restrict__ in, const float* __restrict__ emb,
               float* __restrict__ out_idx) {
    const int cnt    = g_rescue_cnt;
    const int lane   = threadIdx.x & 31;
    const int gwarp  = (blockIdx.x * 256 + threadIdx.x) >> 5;
    const int nwarps = gridDim.x * 8;

    for (int itm = gwarp; itm < cnt; itm += nwarps) {
        const int p  = g_rescue_pts[itm];
        const int b  = p >> 10, hw = p & 1023;
        const float* xin = in + b * CHW + hw;
        float x[D_DIM];
        #pragma unroll
        for (int c = 0; c < D_DIM; ++c) x[c] = __ldg(xin + c * HW);

        float bd = 3.4e38f; int bi = 0x7fffffff;
        #pragma unroll 2
        for (int kk = 0; kk < 16; ++kk) {
            const int code = kk * 32 + lane;
            const float4* er = (const float4*)(emb + code * D_DIM);
            float s0 = 0.0f, s1 = 0.0f;
            #pragma unroll
            for (int j = 0; j < 16; ++j) {
                float4 e4 = __ldg(er + j);
                s0 = fmaf(x[4 * j + 0], e4.x, s0);
                s1 = fmaf(x[4 * j + 1], e4.y, s1);
                s0 = fmaf(x[4 * j + 2], e4.z, s0);
                s1 = fmaf(x[4 * j + 3], e4.w, s1);
            }
            const float d = fmaf(-2.0f, s0 + s1, __ldg(&g_nrm[code]));
            if (d < bd) { bd = d; bi = code; }
        }
        #pragma unroll
        for (int off = 16; off > 0; off >>= 1) {
            float od = __shfl_xor_sync(0xFFFFFFFFu, bd, off);
            int   oi = __shfl_xor_sync(0xFFFFFFFFu, bi, off);
            if (od < bd || (od == bd && oi < bi)) { bd = od; bi = oi; }
        }
        if (lane == 0) out_idx[p] = (float)bi;
    }
}

// ---------------- K3: quantize + exact loss + segment sums ----------------
__global__ __launch_bounds__(256)
void vq_epilogue(const float* __restrict__ in, const float* __restrict__ emb,
                 const float* __restrict__ idxf, float* __restrict__ out_q) {
    const int p  = blockIdx.x * 256 + threadIdx.x;
    const int b  = p >> 10, hw = p & 1023;
    const float* xin = in + b * CHW + hw;
    const int best = (int)idxf[p];

    const float4* erow  = (const float4*)(emb + best * D_DIM);
    float*        qout  = out_q + b * CHW + hw;
    float*        dwrow = g_dw + best * D_DIM;
    float lsum = 0.0f;
    #pragma unroll
    for (int j = 0; j < 16; ++j) {
        float4 e4 = __ldg(erow + j);
        const int c = 4 * j;
        float x0 = xin[(c + 0) * HW];
        float x1 = xin[(c + 1) * HW];
        float x2 = xin[(c + 2) * HW];
        float x3 = xin[(c + 3) * HW];
        float d0 = e4.x - x0, d1 = e4.y - x1, d2 = e4.z - x2, d3 = e4.w - x3;
        qout[(c + 0) * HW] = x0 + d0;
        qout[(c + 1) * HW] = x1 + d1;
        qout[(c + 2) * HW] = x2 + d2;
        qout[(c + 3) * HW] = x3 + d3;
        lsum = fmaf(d0, d0, lsum); lsum = fmaf(d1, d1, lsum);
        lsum = fmaf(d2, d2, lsum); lsum = fmaf(d3, d3, lsum);
        red_add_v4(dwrow + c, x0, x1, x2, x3);
    }
    #pragma unroll
    for (int o = 16; o > 0; o >>= 1) lsum += __shfl_xor_sync(0xFFFFFFFFu, lsum, o);
    if ((threadIdx.x & 31) == 0) atomicAdd(&g_loss_acc, lsum);
    atomicAdd(&g_counts[best], 1.0f);
}

// ---------------- K4a: single-CTA reductions + scalars --------------------
__global__ __launch_bounds__(512, 1)
void vq_finA_kernel(const float* __restrict__ ema_cs, float* __restrict__ out) {
    __shared__ float red[K_CODES];
    const int k = threadIdx.x;

    const float cnt = g_counts[k];
    const float raw = ema_cs[k] * DECAY_C + OMD_C * cnt;

    red[k] = raw;
    __syncthreads();
    #pragma unroll
    for (int o = 256; o > 0; o >>= 1) {
        if (k < o) red[k] += red[k + o];
        __syncthreads();
    }
    const float n = red[0];
    __syncthreads();

    const float ncs = (raw + EPS_C) / (n + (float)K_CODES * EPS_C) * n;
    g_ncs[k] = ncs;
    out[OFF_CS + k] = ncs;

    const float pprob = cnt * (1.0f / (float)NPTS);
    red[k] = pprob * logf(pprob + 1e-10f);
    __syncthreads();
    #pragma unroll
    for (int o = 256; o > 0; o >>= 1) {
        if (k < o) red[k] += red[k + o];
        __syncthreads();
    }
    if (k == 0) {
        out[OFF_PERP] = expf(-red[0]);
        out[0] = BETA_C * g_loss_acc / (float)(NPTS * D_DIM);
        g_loss_acc   = 0.0f;
        g_rescue_cnt = 0;
    }
    g_counts[k] = 0.0f;
}

// ---------------- K4b: parallel EMA-w / new-embedding ---------------------
__global__ __launch_bounds__(512)
void vq_finB_kernel(const float* __restrict__ ema_w, float* __restrict__ out) {
    const int i = blockIdx.x * 512 + threadIdx.x;   // < 32768
    const float w = ema_w[i] * DECAY_C + OMD_C * g_dw[i];
    g_dw[i] = 0.0f;
    out[OFF_W + i] = w;
    out[OFF_E + i] = w / g_ncs[i >> 6];
}

// ---------------- launch ----------------
extern "C" void kernel_launch(void* const* d_in, const int* in_sizes, int n_in,
                              void* d_out, int out_size) {
    const float* in     = (const float*)d_in[0];
    const float* emb    = (const float*)d_in[1];
    const float* ema_w  = (const float*)d_in[2];
    const float* ema_cs = (const float*)d_in[3];
    float* out = (float*)d_out;

    cudaFuncSetAttribute(vq_gemm_argmin,
                         cudaFuncAttributeMaxDynamicSharedMemorySize, SMEM_SZ);

    vq_conv_x<<<256, 256>>>(in);
    vq_conv_e<<<4, 128>>>(emb);
    vq_gemm_argmin<<<128, 512, SMEM_SZ>>>(out + OFF_IDX);
    vq_rescue<<<128, 256>>>(in, emb, out + OFF_IDX);
    vq_epilogue<<<256, 256>>>(in, emb, out + OFF_IDX, out + OFF_Q);
    vq_finA_kernel<<<1, 512>>>(ema_cs, out);
    vq_finB_kernel<<<64, 512>>>(ema_w, out);
}

// round 8
// speedup vs baseline: 1.9350x; 1.2583x over previous
#include <cuda_runtime.h>
#include <cuda_bf16.h>

// ---------------- problem constants ----------------
#define K_CODES 512
#define D_DIM   64
#define NPTS    65536          // 64*32*32
#define HW      1024           // 32*32
#define CHW     65536          // 64*1024
#define BETA_C  0.25f
#define DECAY_C 0.99f
#define OMD_C   0.01f
#define EPS_C   1e-5f
#define TAU     0.005f         // rescue threshold (~10x worst-case 3-term bf16 error)

// output layout (float32, tuple order)
#define OFF_Q    1
#define OFF_PERP 4194305
#define OFF_IDX  4194306
#define OFF_CS   4259842
#define OFF_W    4260354
#define OFF_E    4293122

// ---------------- scratch (zero-init at load; kernels restore zero) --------
__device__ float g_counts[K_CODES];
__device__ float g_dw[K_CODES * D_DIM];
__device__ float g_ncs[K_CODES];
__device__ float g_loss_acc;
__device__ float g_nrm[K_CODES];
__device__ int   g_rescue_pts[NPTS];
__device__ int   g_rescue_cnt;
__device__ __nv_bfloat16 g_Ah[NPTS * D_DIM];    // 8MB  x high bf16
__device__ __nv_bfloat16 g_Al[NPTS * D_DIM];    // 8MB  x residual bf16
__device__ __nv_bfloat16 g_Bh[K_CODES * D_DIM];
__device__ __nv_bfloat16 g_Bl[K_CODES * D_DIM];

// ---------------- helpers ----------------
__device__ __forceinline__ void red_add_v4(float* p, float a, float b, float c, float d) {
    asm volatile("red.global.add.v4.f32 [%0], {%1, %2, %3, %4};"
                 :: "l"(p), "f"(a), "f"(b), "f"(c), "f"(d) : "memory");
}
__device__ __forceinline__ unsigned smem_u32(const void* p) {
    unsigned a;
    asm("{ .reg .u64 t; cvta.to.shared.u64 t, %1; cvt.u32.u64 %0, t; }" : "=r"(a) : "l"(p));
    return a;
}
__device__ __forceinline__ unsigned pack_bf(__nv_bfloat16 a, __nv_bfloat16 b) {
    return (unsigned)__bfloat16_as_ushort(a) | ((unsigned)__bfloat16_as_ushort(b) << 16);
}
// monotonic float -> orderable uint mapping
__device__ __forceinline__ unsigned f2ord(float f) {
    unsigned u = __float_as_uint(f);
    return (u & 0x80000000u) ? ~u : (u | 0x80000000u);
}
#define SW128(o) ((o) ^ (((o) >> 3) & 0x70))

// warp-level bf16 MMA (sm_80+ baseline PTX, no 'a' suffix needed)
__device__ __forceinline__ void mma_bf16(float* c, const unsigned* a,
                                         unsigned b0, unsigned b1) {
    asm volatile(
        "mma.sync.aligned.m16n8k16.row.col.f32.bf16.bf16.f32 "
        "{%0,%1,%2,%3}, {%4,%5,%6,%7}, {%8,%9}, {%0,%1,%2,%3};"
        : "+f"(c[0]), "+f"(c[1]), "+f"(c[2]), "+f"(c[3])
        : "r"(a[0]), "r"(a[1]), "r"(a[2]), "r"(a[3]), "r"(b0), "r"(b1));
}
__device__ __forceinline__ void ldmx2(unsigned& r0, unsigned& r1, unsigned saddr) {
    asm volatile("ldmatrix.sync.aligned.m8n8.x2.shared.b16 {%0,%1}, [%2];"
                 : "=r"(r0), "=r"(r1) : "r"(saddr));
}
__device__ __forceinline__ void upd(float& best, float& sec, int& idx, float d, int c) {
    if (d < best) { sec = best; best = d; idx = c; }
    else if (d < sec) { sec = d; }
}

// ---------------- K1a: convert x -> bf16 hi/lo, [point][dim] ----------------
__global__ __launch_bounds__(256)
void vq_conv_x(const float* __restrict__ in) {
    const int p  = blockIdx.x * 256 + threadIdx.x;
    const int b  = p >> 10, hw = p & 1023;
    const float* x = in + b * CHW + hw;
    uint4* Ah = (uint4*)g_Ah;
    uint4* Al = (uint4*)g_Al;
    #pragma unroll
    for (int j = 0; j < 8; ++j) {
        unsigned h[4], l[4];
        #pragma unroll
        for (int q = 0; q < 4; ++q) {
            float v0 = x[(8 * j + 2 * q) * HW];
            float v1 = x[(8 * j + 2 * q + 1) * HW];
            __nv_bfloat16 h0 = __float2bfloat16(v0), h1 = __float2bfloat16(v1);
            __nv_bfloat16 l0 = __float2bfloat16(v0 - __bfloat162float(h0));
            __nv_bfloat16 l1 = __float2bfloat16(v1 - __bfloat162float(h1));
            h[q] = pack_bf(h0, h1);
            l[q] = pack_bf(l0, l1);
        }
        Ah[p * 8 + j] = make_uint4(h[0], h[1], h[2], h[3]);
        Al[p * 8 + j] = make_uint4(l[0], l[1], l[2], l[3]);
    }
}

// ---------------- K1b: convert embedding -> bf16 hi/lo + fp32 norms --------
__global__ __launch_bounds__(128)
void vq_conv_e(const float* __restrict__ emb) {
    const int k = blockIdx.x * 128 + threadIdx.x;   // grid 4 -> 512
    const float* e = emb + k * D_DIM;
    uint4* Bh = (uint4*)g_Bh;
    uint4* Bl = (uint4*)g_Bl;
    float s = 0.0f;
    #pragma unroll
    for (int j = 0; j < 8; ++j) {
        unsigned h[4], l[4];
        #pragma unroll
        for (int q = 0; q < 4; ++q) {
            float v0 = e[8 * j + 2 * q];
            float v1 = e[8 * j + 2 * q + 1];
            s = fmaf(v0, v0, s);
            s = fmaf(v1, v1, s);
            __nv_bfloat16 h0 = __float2bfloat16(v0), h1 = __float2bfloat16(v1);
            __nv_bfloat16 l0 = __float2bfloat16(v0 - __bfloat162float(h0));
            __nv_bfloat16 l1 = __float2bfloat16(v1 - __bfloat162float(h1));
            h[q] = pack_bf(h0, h1);
            l[q] = pack_bf(l0, l1);
        }
        Bh[k * 8 + j] = make_uint4(h[0], h[1], h[2], h[3]);
        Bl[k * 8 + j] = make_uint4(l[0], l[1], l[2], l[3]);
    }
    g_nrm[k] = s;
}

// ---------------- K2: mma.sync GEMM + argmin -------------------------------
// 128 CTAs x 512 thr (16 warps). Each warp: 32 points (two m16 tiles), 512 codes.
// smem: nrm 2KB @0 | Bh 64KB @2048 | Bl 64KB @67584  -> 133120 B
#define SM_NRM 0
#define SM_BH  2048
#define SM_BL  67584
#define SMEM_SZ 133120

__global__ __launch_bounds__(512, 1)
void vq_gemm_argmin(float* __restrict__ out_idx) {
    extern __shared__ char smem[];
    const unsigned sb = smem_u32(smem);
    const int tid  = threadIdx.x;
    const int wid  = tid >> 5;
    const int lane = tid & 31;

    // stage codebook (swizzled) + norms once per CTA
    {
        const uint4* bh = (const uint4*)g_Bh;
        const uint4* bl = (const uint4*)g_Bl;
        #pragma unroll
        for (int i = tid; i < K_CODES * 8; i += 512) {
            unsigned off = SW128((unsigned)(i * 16));
            *(uint4*)(smem + SM_BH + off) = bh[i];
            *(uint4*)(smem + SM_BL + off) = bl[i];
        }
        float* nsh = (float*)(smem + SM_NRM);
        if (tid < K_CODES) nsh[tid] = g_nrm[tid];
    }
    __syncthreads();

    const float* nrm_sh = (const float*)(smem + SM_NRM);
    const int r    = lane & 7;
    const int half = (lane >> 3) & 1;
    const unsigned lane_rel = (unsigned)(r * 128);
    const unsigned qk = lane & 3;
    const unsigned qr = lane >> 2;

    const int p0 = blockIdx.x * 512 + wid * 32;   // 32 points per warp

    // A fragments for both 16-row tiles, 4 k-steps, hi+lo
    unsigned ah[2][16], al[2][16];
    #pragma unroll
    for (int t = 0; t < 2; ++t) {
        const __nv_bfloat16* A0 = g_Ah + (size_t)(p0 + t * 16 + qr) * D_DIM;
        const __nv_bfloat16* A1 = g_Al + (size_t)(p0 + t * 16 + qr) * D_DIM;
        #pragma unroll
        for (int kk = 0; kk < 4; ++kk) {
            const int e0 = kk * 16 + 2 * (int)qk;
            ah[t][kk*4+0] = *(const unsigned*)(A0 + e0);
            ah[t][kk*4+1] = *(const unsigned*)(A0 + 8 * D_DIM + e0);
            ah[t][kk*4+2] = *(const unsigned*)(A0 + e0 + 8);
            ah[t][kk*4+3] = *(const unsigned*)(A0 + 8 * D_DIM + e0 + 8);
            al[t][kk*4+0] = *(const unsigned*)(A1 + e0);
            al[t][kk*4+1] = *(const unsigned*)(A1 + 8 * D_DIM + e0);
            al[t][kk*4+2] = *(const unsigned*)(A1 + e0 + 8);
            al[t][kk*4+3] = *(const unsigned*)(A1 + 8 * D_DIM + e0 + 8);
        }
    }

    // slot s = t*2 + rowgroup (rowgroup 0: row qr, 1: row qr+8)
    float best[4] = {3.4e38f, 3.4e38f, 3.4e38f, 3.4e38f};
    float sec [4] = {3.4e38f, 3.4e38f, 3.4e38f, 3.4e38f};
    int   idx [4] = {0, 0, 0, 0};

    #pragma unroll 1
    for (int nt = 0; nt < 64; ++nt) {
        float c0[4] = {0.f, 0.f, 0.f, 0.f};
        float c1[4] = {0.f, 0.f, 0.f, 0.f};
        const unsigned ntoff = (unsigned)(nt * 1024) + lane_rel;
        #pragma unroll
        for (int kk = 0; kk < 4; ++kk) {
            const unsigned rel = ntoff + (((unsigned)(kk * 32 + half * 16)) ^ (unsigned)(r * 16));
            unsigned bh0, bh1, bl0, bl1;
            ldmx2(bh0, bh1, sb + SM_BH + rel);
            ldmx2(bl0, bl1, sb + SM_BL + rel);
            mma_bf16(c0, &ah[0][kk*4], bh0, bh1);
            mma_bf16(c0, &ah[0][kk*4], bl0, bl1);
            mma_bf16(c0, &al[0][kk*4], bh0, bh1);
            mma_bf16(c1, &ah[1][kk*4], bh0, bh1);
            mma_bf16(c1, &ah[1][kk*4], bl0, bl1);
            mma_bf16(c1, &al[1][kk*4], bh0, bh1);
        }
        const int colb = nt * 8 + 2 * (int)qk;
        const float n0 = nrm_sh[colb];
        const float n1 = nrm_sh[colb + 1];
        upd(best[0], sec[0], idx[0], fmaf(-2.f, c0[0], n0), colb);
        upd(best[0], sec[0], idx[0], fmaf(-2.f, c0[1], n1), colb + 1);
        upd(best[1], sec[1], idx[1], fmaf(-2.f, c0[2], n0), colb);
        upd(best[1], sec[1], idx[1], fmaf(-2.f, c0[3], n1), colb + 1);
        upd(best[2], sec[2], idx[2], fmaf(-2.f, c1[0], n0), colb);
        upd(best[2], sec[2], idx[2], fmaf(-2.f, c1[1], n1), colb + 1);
        upd(best[3], sec[3], idx[3], fmaf(-2.f, c1[2], n0), colb);
        upd(best[3], sec[3], idx[3], fmaf(-2.f, c1[3], n1), colb + 1);
    }

    // merge across the 4 lanes of each quad
    #pragma unroll
    for (int s = 0; s < 4; ++s) {
        #pragma unroll
        for (int o = 1; o <= 2; o <<= 1) {
            float ob = __shfl_xor_sync(0xFFFFFFFFu, best[s], o);
            float os = __shfl_xor_sync(0xFFFFFFFFu, sec[s],  o);
            int   oi = __shfl_xor_sync(0xFFFFFFFFu, idx[s],  o);
            if (ob < best[s] || (ob == best[s] && oi < idx[s])) {
                sec[s] = fminf(best[s], os); best[s] = ob; idx[s] = oi;
            } else sec[s] = fminf(sec[s], ob);
        }
    }

    if (qk == 0) {
        #pragma unroll
        for (int s = 0; s < 4; ++s) {
            const int p = p0 + (s >> 1) * 16 + (int)qr + (s & 1) * 8;
            out_idx[p] = (float)idx[s];
            if (sec[s] - best[s] < TAU) {
                int slot = atomicAdd(&g_rescue_cnt, 1);
                g_rescue_pts[slot] = p;
            }
        }
    }
}

// ---------------- K2b: exact fp32 rescue, one CTA per point ---------------
// 256 CTAs x 256 thr; each thread covers 2 codes, block-wide exact argmin.
__global__ __launch_bounds__(256)
void vq_rescue(const float* __restrict__ in, const float* __restrict__ emb,
               float* __restrict__ out_idx) {
    __shared__ float xs[D_DIM];
    __shared__ unsigned long long red[256];
    const int tid = threadIdx.x;
    const int cnt = g_rescue_cnt;

    for (int itm = blockIdx.x; itm < cnt; itm += gridDim.x) {
        const int p  = g_rescue_pts[itm];
        const int b  = p >> 10, hw = p & 1023;
        if (tid < D_DIM) xs[tid] = __ldg(in + b * CHW + tid * HW + hw);
        __syncthreads();

        unsigned long long bestp = ~0ull;
        #pragma unroll
        for (int cc = 0; cc < 2; ++cc) {
            const int code = cc * 256 + tid;
            const float4* er = (const float4*)(emb + code * D_DIM);
            float s0 = 0.0f, s1 = 0.0f;
            #pragma unroll
            for (int j = 0; j < 16; ++j) {
                float4 e4 = __ldg(er + j);
                s0 = fmaf(xs[4 * j + 0], e4.x, s0);
                s1 = fmaf(xs[4 * j + 1], e4.y, s1);
                s0 = fmaf(xs[4 * j + 2], e4.z, s0);
                s1 = fmaf(xs[4 * j + 3], e4.w, s1);
            }
            const float d = fmaf(-2.0f, s0 + s1, __ldg(&g_nrm[code]));
            const unsigned long long pk =
                ((unsigned long long)f2ord(d) << 32) | (unsigned)code;
            bestp = (pk < bestp) ? pk : bestp;
        }
        red[tid] = bestp;
        __syncthreads();
        #pragma unroll
        for (int o = 128; o > 0; o >>= 1) {
            if (tid < o) {
                unsigned long long v = red[tid + o];
                if (v < red[tid]) red[tid] = v;
            }
            __syncthreads();
        }
        if (tid == 0) out_idx[p] = (float)(unsigned)(red[0] & 0xffffffffu);
        __syncthreads();
    }
}

// ---------------- K3: quantize + exact loss + segment sums ----------------
__global__ __launch_bounds__(256)
void vq_epilogue(const float* __restrict__ in, const float* __restrict__ emb,
                 const float* __restrict__ idxf, float* __restrict__ out_q) {
    const int p  = blockIdx.x * 256 + threadIdx.x;
    const int b  = p >> 10, hw = p & 1023;
    const float* xin = in + b * CHW + hw;
    const int best = (int)idxf[p];

    const float4* erow  = (const float4*)(emb + best * D_DIM);
    float*        qout  = out_q + b * CHW + hw;
    float*        dwrow = g_dw + best * D_DIM;
    float lsum = 0.0f;
    #pragma unroll
    for (int j = 0; j < 16; ++j) {
        float4 e4 = __ldg(erow + j);
        const int c = 4 * j;
        float x0 = xin[(c + 0) * HW];
        float x1 = xin[(c + 1) * HW];
        float x2 = xin[(c + 2) * HW];
        float x3 = xin[(c + 3) * HW];
        float d0 = e4.x - x0, d1 = e4.y - x1, d2 = e4.z - x2, d3 = e4.w - x3;
        qout[(c + 0) * HW] = x0 + d0;
        qout[(c + 1) * HW] = x1 + d1;
        qout[(c + 2) * HW] = x2 + d2;
        qout[(c + 3) * HW] = x3 + d3;
        lsum = fmaf(d0, d0, lsum); lsum = fmaf(d1, d1, lsum);
        lsum = fmaf(d2, d2, lsum); lsum = fmaf(d3, d3, lsum);
        red_add_v4(dwrow + c, x0, x1, x2, x3);
    }
    #pragma unroll
    for (int o = 16; o > 0; o >>= 1) lsum += __shfl_xor_sync(0xFFFFFFFFu, lsum, o);
    if ((threadIdx.x & 31) == 0) atomicAdd(&g_loss_acc, lsum);
    atomicAdd(&g_counts[best], 1.0f);
}

// ---------------- K4a: single-CTA reductions + scalars --------------------
__global__ __launch_bounds__(512, 1)
void vq_finA_kernel(const float* __restrict__ ema_cs, float* __restrict__ out) {
    __shared__ float red[K_CODES];
    const int k = threadIdx.x;

    const float cnt = g_counts[k];
    const float raw = ema_cs[k] * DECAY_C + OMD_C * cnt;

    red[k] = raw;
    __syncthreads();
    #pragma unroll
    for (int o = 256; o > 0; o >>= 1) {
        if (k < o) red[k] += red[k + o];
        __syncthreads();
    }
    const float n = red[0];
    __syncthreads();

    const float ncs = (raw + EPS_C) / (n + (float)K_CODES * EPS_C) * n;
    g_ncs[k] = ncs;
    out[OFF_CS + k] = ncs;

    const float pprob = cnt * (1.0f / (float)NPTS);
    red[k] = pprob * logf(pprob + 1e-10f);
    __syncthreads();
    #pragma unroll
    for (int o = 256; o > 0; o >>= 1) {
        if (k < o) red[k] += red[k + o];
        __syncthreads();
    }
    if (k == 0) {
        out[OFF_PERP] = expf(-red[0]);
        out[0] = BETA_C * g_loss_acc / (float)(NPTS * D_DIM);
        g_loss_acc   = 0.0f;
        g_rescue_cnt = 0;
    }
    g_counts[k] = 0.0f;
}

// ---------------- K4b: parallel EMA-w / new-embedding ---------------------
__global__ __launch_bounds__(512)
void vq_finB_kernel(const float* __restrict__ ema_w, float* __restrict__ out) {
    const int i = blockIdx.x * 512 + threadIdx.x;   // < 32768
    const float w = ema_w[i] * DECAY_C + OMD_C * g_dw[i];
    g_dw[i] = 0.0f;
    out[OFF_W + i] = w;
    out[OFF_E + i] = w / g_ncs[i >> 6];
}

// ---------------- launch ----------------
extern "C" void kernel_launch(void* const* d_in, const int* in_sizes, int n_in,
                              void* d_out, int out_size) {
    const float* in     = (const float*)d_in[0];
    const float* emb    = (const float*)d_in[1];
    const float* ema_w  = (const float*)d_in[2];
    const float* ema_cs = (const float*)d_in[3];
    float* out = (float*)d_out;

    cudaFuncSetAttribute(vq_gemm_argmin,
                         cudaFuncAttributeMaxDynamicSharedMemorySize, SMEM_SZ);

    vq_conv_x<<<256, 256>>>(in);
    vq_conv_e<<<4, 128>>>(emb);
    vq_gemm_argmin<<<128, 512, SMEM_SZ>>>(out + OFF_IDX);
    vq_rescue<<<256, 256>>>(in, emb, out + OFF_IDX);
    vq_epilogue<<<256, 256>>>(in, emb, out + OFF_IDX, out + OFF_Q);
    vq_finA_kernel<<<1, 512>>>(ema_cs, out);
    vq_finB_kernel<<<64, 512>>>(ema_w, out);
}